// round 8
// baseline (speedup 1.0000x reference)
#include <cuda_runtime.h>
#include <math.h>
#include <stdint.h>

#define NPIX 16384
constexpr int NT = 1024;

__device__ float g_te[8 * 1024];
__device__ float g_film[8 * 128];

// ---------------- helpers ----------------------------------------------------
__device__ __forceinline__ float rna(float x) {
    float y; asm("cvt.rna.tf32.f32 %0, %1;" : "=f"(y) : "f"(x)); return y;
}
__device__ __forceinline__ float ex2f(float x) {
    float y; asm("ex2.approx.f32 %0, %1;" : "=f"(y) : "f"(x)); return y;
}
__device__ __forceinline__ float geluf(float v) {
    return 0.5f * v * (1.f + erff(v * 0.70710678118654752f));
}
__device__ __forceinline__ unsigned long long pk2(float a, float b) {
    unsigned long long r; asm("mov.b64 %0, {%1, %2};" : "=l"(r) : "f"(a), "f"(b)); return r;
}
__device__ __forceinline__ float2 upk(unsigned long long a) {
    float2 f; asm("mov.b64 {%0, %1}, %2;" : "=f"(f.x), "=f"(f.y) : "l"(a)); return f;
}
__device__ __forceinline__ unsigned long long ffma2(unsigned long long a, unsigned long long b, unsigned long long c) {
    unsigned long long d; asm("fma.rn.f32x2 %0, %1, %2, %3;" : "=l"(d) : "l"(a), "l"(b), "l"(c)); return d;
}
__device__ __forceinline__ unsigned long long fmul2(unsigned long long a, unsigned long long b) {
    unsigned long long d; asm("mul.rn.f32x2 %0, %1, %2;" : "=l"(d) : "l"(a), "l"(b)); return d;
}

// m16n8k8 tf32 mma: D(16x8) += A(16x8,row) * B(8x8,col-frag)
__device__ __forceinline__ void mma8(float* d, uint32_t a0, uint32_t a1, uint32_t a2,
                                     uint32_t a3, uint32_t b0, uint32_t b1) {
    asm volatile(
        "mma.sync.aligned.m16n8k8.row.col.f32.tf32.tf32.f32 "
        "{%0,%1,%2,%3}, {%4,%5,%6,%7}, {%8,%9}, {%0,%1,%2,%3};"
        : "+f"(d[0]), "+f"(d[1]), "+f"(d[2]), "+f"(d[3])
        : "r"(a0), "r"(a1), "r"(a2), "r"(a3), "r"(b0), "r"(b1));
}

// GEMM: D[64 out][128 tok] = W[64 out][64 in] (A, stride 68) @ Act[64 in][128 tok] (B, stride 136)
// warp w: rows tt=16*(w&3), cols cc=16*(w>>2); per-thread frag ids g=lane>>2, t=lane&3.
__device__ __forceinline__ void gemm_loop(const float* __restrict__ Aw,
                                          const float* __restrict__ Bact,
                                          int tt, int cc, int g, int t, float acc[2][4]) {
    const float* a0p = Aw + (tt + g) * 68 + t;
    const float* a1p = a0p + 8 * 68;
    const float* b0p = Bact + t * 136 + cc + g;
    #pragma unroll
    for (int ks = 0; ks < 8; ks++) {
        uint32_t a0 = __float_as_uint(a0p[8 * ks]);
        uint32_t a1 = __float_as_uint(a1p[8 * ks]);
        uint32_t a2 = __float_as_uint(a0p[8 * ks + 4]);
        uint32_t a3 = __float_as_uint(a1p[8 * ks + 4]);
        uint32_t b0 = __float_as_uint(b0p[(8 * ks) * 136]);
        uint32_t b1 = __float_as_uint(b0p[(8 * ks + 4) * 136]);
        mma8(acc[0], a0, a1, a2, a3, b0, b1);
        b0 = __float_as_uint(b0p[(8 * ks) * 136 + 8]);
        b1 = __float_as_uint(b0p[(8 * ks + 4) * 136 + 8]);
        mma8(acc[1], a0, a1, a2, a3, b0, b1);
    }
}

// ---------------------------------------------------------------------------
__global__ void __launch_bounds__(128) pool_kernel(const float* __restrict__ te) {
    const int tid = threadIdx.x, lane = tid & 31, jc = tid >> 5;
    const int ic = blockIdx.x & 3, c = (blockIdx.x >> 2) & 63, b = blockIdx.x >> 8;
    const float* src = te + ((size_t)(b * 64 + c)) * NPIX + (size_t)(ic * 32) * 128 + tid;
    float acc = 0.f;
    #pragma unroll 8
    for (int r = 0; r < 32; r++) acc += src[r * 128];
    for (int off = 16; off; off >>= 1) acc += __shfl_down_sync(0xffffffffu, acc, off);
    if (lane == 0) g_te[b * 1024 + c * 16 + ic * 4 + jc] = acc * (1.0f / 1024.0f);
}

__global__ void __launch_bounds__(128) film_kernel(
    const float* __restrict__ m1w, const float* __restrict__ m1b,
    const float* __restrict__ m2w, const float* __restrict__ m2b) {
    __shared__ float ste[1024];
    __shared__ float shm[128];
    const int b = blockIdx.x, tid = threadIdx.x;
    for (int i = tid; i < 1024; i += 128) ste[i] = g_te[b * 1024 + i];
    __syncthreads();
    float acc = m1b[tid];
    for (int k = 0; k < 1024; k++) acc = fmaf(ste[k], m1w[k * 128 + tid], acc);
    shm[tid] = acc > 0.f ? acc : 0.01f * acc;
    __syncthreads();
    float acc2 = m2b[tid];
    #pragma unroll 4
    for (int k = 0; k < 128; k++) acc2 = fmaf(shm[k], m2w[k * 128 + tid], acc2);
    g_film[b * 128 + tid] = acc2;
}

// ---------------------------------------------------------------------------
// smem float offsets
constexpr int O_TP  = 0;       // prior -> h      [64 ch][136]
constexpr int O_TB  = 8704;    // LN1out -> attn -> hn  [64][136]
constexpr int O_TXQ = 17408;   // x[64][136] -> Q[128][68] -> gelu[64][136] -> hfin[64][136]
constexpr int O_TK  = 26112;   // K token-major [128][68]
constexpr int O_TV  = 34816;   // V token-major [128][68]
constexpr int O_W0  = 43520;   // A-slot 0 [64][68]
constexpr int O_W1  = 47872;   // A-slot 1 [64][68]
constexpr int O_MU  = 52224, O_RS = 52352;
constexpr int O_PS  = 52480, O_PQ = 53504;   // LN partials [1024] each
constexpr int O_GM  = 54528, O_BT = 54592;
constexpr int SMEM_FLOATS = 54656;
constexpr int SMEM_BYTES = SMEM_FLOATS * 4;  // 218624

// stage W^T: dst[o*68 + k] = rna(src[k*RL + co + o]),  o,k in [0,64)
__device__ __forceinline__ void stageWT(float* dst, const float* __restrict__ src,
                                        int RL, int co, int tid) {
    #pragma unroll
    for (int i = tid; i < 4096; i += NT) {
        int o = i & 63, k = i >> 6;
        dst[o * 68 + k] = rna(src[k * RL + co + o]);
    }
}

__global__ void __launch_bounds__(NT, 1) fused_kernel(
    const float* __restrict__ x, const float* __restrict__ te,
    const float* __restrict__ qw, const float* __restrict__ qb,
    const float* __restrict__ kw, const float* __restrict__ kb,
    const float* __restrict__ vw, const float* __restrict__ vb,
    const float* __restrict__ ow, const float* __restrict__ ob,
    const float* __restrict__ ln1w, const float* __restrict__ ln1b,
    const float* __restrict__ ln2w, const float* __restrict__ ln2b,
    const float* __restrict__ fc1w, const float* __restrict__ fc1b,
    const float* __restrict__ fc2w, const float* __restrict__ fc2b,
    const float* __restrict__ cw, const float* __restrict__ cb,
    float* __restrict__ out) {
    extern __shared__ __align__(16) float s[];
    const int tid = threadIdx.x;
    const int w = tid >> 5, lane = tid & 31;
    const int g = lane >> 2, t = lane & 3;
    const int tt = 16 * (w & 3);     // output-row tile base (M=64)
    const int cc = 16 * (w >> 2);    // token tile base (N=128)
    const int b = blockIdx.x >> 7, row = blockIdx.x & 127;
    const size_t base = (size_t)b * 64 * NPIX + (size_t)row * 128;

    // ---- stage: x, prior (direct ch-major copies), kw^T, vw^T
    #pragma unroll
    for (int i = tid; i < 2048; i += NT) {
        int c = i >> 5, t4 = (i & 31) * 4;
        *reinterpret_cast<float4*>(&s[O_TXQ + c * 136 + t4]) =
            *reinterpret_cast<const float4*>(&x[base + (size_t)c * NPIX + t4]);
        *reinterpret_cast<float4*>(&s[O_TP + c * 136 + t4]) =
            *reinterpret_cast<const float4*>(&te[base + (size_t)c * NPIX + t4]);
    }
    stageWT(s + O_W0, kw, 64, 0, tid);
    stageWT(s + O_W1, vw, 64, 0, tid);
    __syncthreads();

    // ---- LN1 stats (partials over 8-channel groups)
    {
        int tok = tid & 127, cg = tid >> 7;
        float ps = 0.f, pq = 0.f;
        #pragma unroll
        for (int j = 0; j < 8; j++) {
            float v = s[O_TP + (cg * 8 + j) * 136 + tok];
            ps += v; pq += v * v;
        }
        s[O_PS + tid] = ps; s[O_PQ + tid] = pq;
    }
    __syncthreads();
    if (tid < 128) {
        float sum = 0.f, sq = 0.f;
        #pragma unroll
        for (int j = 0; j < 8; j++) { sum += s[O_PS + tid + 128 * j]; sq += s[O_PQ + tid + 128 * j]; }
        float mu = sum * (1.f / 64.f);
        float var = fmaxf(sq * (1.f / 64.f) - mu * mu, 0.f);
        s[O_MU + tid] = mu; s[O_RS + tid] = rsqrtf(var + 1e-5f);
    }
    __syncthreads();
    // LN1 out -> TB (rna)
    #pragma unroll
    for (int i = tid; i < 2048; i += NT) {
        int c = i >> 5, t4 = (i & 31) * 4;
        float4 p = *reinterpret_cast<const float4*>(&s[O_TP + c * 136 + t4]);
        float4 mu = *reinterpret_cast<const float4*>(&s[O_MU + t4]);
        float4 rs = *reinterpret_cast<const float4*>(&s[O_RS + t4]);
        float lw = ln1w[c], lb = ln1b[c];
        float4 o;
        o.x = rna((p.x - mu.x) * rs.x * lw + lb);
        o.y = rna((p.y - mu.y) * rs.y * lw + lb);
        o.z = rna((p.z - mu.z) * rs.z * lw + lb);
        o.w = rna((p.w - mu.w) * rs.w * lw + lb);
        *reinterpret_cast<float4*>(&s[O_TB + c * 136 + t4]) = o;
    }
    __syncthreads();

    // ---- K, V GEMMs (B = x)
    float accK[2][4] = {}, accV[2][4] = {};
    gemm_loop(s + O_W0, s + O_TXQ, tt, cc, g, t, accK);
    gemm_loop(s + O_W1, s + O_TXQ, tt, cc, g, t, accV);
    __syncthreads();
    // epi K,V -> token-major; stage qw^T -> W0
    {
        int o0 = tt + g, o1 = o0 + 8;
        float kb0 = kb[o0], kb1 = kb[o1], vb0 = vb[o0], vb1 = vb[o1];
        #pragma unroll
        for (int nt = 0; nt < 2; nt++) {
            int c0 = cc + 8 * nt + 2 * t;
            s[O_TK + (c0 + 0) * 68 + o0] = accK[nt][0] + kb0;
            s[O_TK + (c0 + 1) * 68 + o0] = accK[nt][1] + kb0;
            s[O_TK + (c0 + 0) * 68 + o1] = accK[nt][2] + kb1;
            s[O_TK + (c0 + 1) * 68 + o1] = accK[nt][3] + kb1;
            s[O_TV + (c0 + 0) * 68 + o0] = accV[nt][0] + vb0;
            s[O_TV + (c0 + 1) * 68 + o0] = accV[nt][1] + vb0;
            s[O_TV + (c0 + 0) * 68 + o1] = accV[nt][2] + vb1;
            s[O_TV + (c0 + 1) * 68 + o1] = accV[nt][3] + vb1;
        }
    }
    stageWT(s + O_W0, qw, 64, 0, tid);
    __syncthreads();

    // ---- Q GEMM (B = LN1out)
    float accQ[2][4] = {};
    gemm_loop(s + O_W0, s + O_TB, tt, cc, g, t, accQ);
    __syncthreads();
    // epi Q -> TXQ token-major, (v + qb) * QS (fold 1/sqrt(hd) * log2e); stage ow^T -> W1
    {
        const float QS = 0.72134752044448170f;
        int o0 = tt + g, o1 = o0 + 8;
        float qb0 = qb[o0], qb1 = qb[o1];
        #pragma unroll
        for (int nt = 0; nt < 2; nt++) {
            int c0 = cc + 8 * nt + 2 * t;
            s[O_TXQ + (c0 + 0) * 68 + o0] = (accQ[nt][0] + qb0) * QS;
            s[O_TXQ + (c0 + 1) * 68 + o0] = (accQ[nt][1] + qb0) * QS;
            s[O_TXQ + (c0 + 0) * 68 + o1] = (accQ[nt][2] + qb1) * QS;
            s[O_TXQ + (c0 + 1) * 68 + o1] = (accQ[nt][3] + qb1) * QS;
        }
    }
    stageWT(s + O_W1, ow, 64, 0, tid);
    __syncthreads();

    // ---- attention: warp -> head (w>>1), half (w&1); thread: 2 tokens, 1 head
    float4 r0v, r1v;
    {
        int hh = w >> 1;
        int r0 = 64 * (w & 1) + lane, r1 = r0 + 32;
        float4 q0 = *reinterpret_cast<const float4*>(&s[O_TXQ + r0 * 68 + 4 * hh]);
        float4 q1 = *reinterpret_cast<const float4*>(&s[O_TXQ + r1 * 68 + 4 * hh]);
        unsigned long long q0a = pk2(q0.x, q0.y), q0b = pk2(q0.z, q0.w);
        unsigned long long q1a = pk2(q1.x, q1.y), q1b = pk2(q1.z, q1.w);
        unsigned long long a0a = 0, a0b = 0, a1a = 0, a1b = 0;
        float l0 = 0.f, l1 = 0.f;
        const float* Kp = s + O_TK + 4 * hh;
        const float* Vp = s + O_TV + 4 * hh;
        #pragma unroll 4
        for (int k = 0; k < 128; k++) {
            ulonglong2 kv = *reinterpret_cast<const ulonglong2*>(Kp + k * 68);
            ulonglong2 vv = *reinterpret_cast<const ulonglong2*>(Vp + k * 68);
            float2 p0 = upk(ffma2(q0b, kv.y, fmul2(q0a, kv.x)));
            float e0 = ex2f(p0.x + p0.y);
            float2 p1 = upk(ffma2(q1b, kv.y, fmul2(q1a, kv.x)));
            float e1 = ex2f(p1.x + p1.y);
            l0 += e0; l1 += e1;
            unsigned long long e0d = pk2(e0, e0), e1d = pk2(e1, e1);
            a0a = ffma2(e0d, vv.x, a0a); a0b = ffma2(e0d, vv.y, a0b);
            a1a = ffma2(e1d, vv.x, a1a); a1b = ffma2(e1d, vv.y, a1b);
        }
        float i0 = __fdividef(1.f, l0), i1 = __fdividef(1.f, l1);
        float2 f0a = upk(a0a), f0b = upk(a0b), f1a = upk(a1a), f1b = upk(a1b);
        r0v = make_float4(rna(f0a.x * i0), rna(f0a.y * i0), rna(f0b.x * i0), rna(f0b.y * i0));
        r1v = make_float4(rna(f1a.x * i1), rna(f1a.y * i1), rna(f1b.x * i1), rna(f1b.y * i1));
    }
    __syncthreads();
    // attn out -> TB ch-major
    {
        int hh = w >> 1;
        int r0 = 64 * (w & 1) + lane, r1 = r0 + 32;
        s[O_TB + (4 * hh + 0) * 136 + r0] = r0v.x;
        s[O_TB + (4 * hh + 1) * 136 + r0] = r0v.y;
        s[O_TB + (4 * hh + 2) * 136 + r0] = r0v.z;
        s[O_TB + (4 * hh + 3) * 136 + r0] = r0v.w;
        s[O_TB + (4 * hh + 0) * 136 + r1] = r1v.x;
        s[O_TB + (4 * hh + 1) * 136 + r1] = r1v.y;
        s[O_TB + (4 * hh + 2) * 136 + r1] = r1v.z;
        s[O_TB + (4 * hh + 3) * 136 + r1] = r1v.w;
    }
    __syncthreads();

    // ---- O GEMM (B = attn)
    float accO[2][4] = {};
    gemm_loop(s + O_W1, s + O_TB, tt, cc, g, t, accO);
    __syncthreads();
    // epi O: h = v + ob + prior -> TP; stage fc1_0 -> W0, fc2_0 -> W1, film
    {
        int o0 = tt + g, o1 = o0 + 8;
        float ob0 = ob[o0], ob1 = ob[o1];
        #pragma unroll
        for (int nt = 0; nt < 2; nt++) {
            int c0 = cc + 8 * nt + 2 * t;
            float2 p0 = *reinterpret_cast<const float2*>(&s[O_TP + o0 * 136 + c0]);
            float2 p1 = *reinterpret_cast<const float2*>(&s[O_TP + o1 * 136 + c0]);
            p0.x += accO[nt][0] + ob0; p0.y += accO[nt][1] + ob0;
            p1.x += accO[nt][2] + ob1; p1.y += accO[nt][3] + ob1;
            *reinterpret_cast<float2*>(&s[O_TP + o0 * 136 + c0]) = p0;
            *reinterpret_cast<float2*>(&s[O_TP + o1 * 136 + c0]) = p1;
        }
    }
    stageWT(s + O_W0, fc1w, 256, 0, tid);
    stageWT(s + O_W1, fc2w, 64, 0, tid);
    if (tid < 64) {
        s[O_GM + tid] = g_film[b * 128 + tid];
        s[O_BT + tid] = g_film[b * 128 + 64 + tid];
    }
    __syncthreads();

    // ---- LN2 stats
    {
        int tok = tid & 127, cg = tid >> 7;
        float ps = 0.f, pq = 0.f;
        #pragma unroll
        for (int j = 0; j < 8; j++) {
            float v = s[O_TP + (cg * 8 + j) * 136 + tok];
            ps += v; pq += v * v;
        }
        s[O_PS + tid] = ps; s[O_PQ + tid] = pq;
    }
    __syncthreads();
    if (tid < 128) {
        float sum = 0.f, sq = 0.f;
        #pragma unroll
        for (int j = 0; j < 8; j++) { sum += s[O_PS + tid + 128 * j]; sq += s[O_PQ + tid + 128 * j]; }
        float mu = sum * (1.f / 64.f);
        float var = fmaxf(sq * (1.f / 64.f) - mu * mu, 0.f);
        s[O_MU + tid] = mu; s[O_RS + tid] = rsqrtf(var + 1e-5f);
    }
    __syncthreads();
    // LN2 out -> TB (rna)
    #pragma unroll
    for (int i = tid; i < 2048; i += NT) {
        int c = i >> 5, t4 = (i & 31) * 4;
        float4 p = *reinterpret_cast<const float4*>(&s[O_TP + c * 136 + t4]);
        float4 mu = *reinterpret_cast<const float4*>(&s[O_MU + t4]);
        float4 rs = *reinterpret_cast<const float4*>(&s[O_RS + t4]);
        float lw = ln2w[c], lb = ln2b[c];
        float4 o;
        o.x = rna((p.x - mu.x) * rs.x * lw + lb);
        o.y = rna((p.y - mu.y) * rs.y * lw + lb);
        o.z = rna((p.z - mu.z) * rs.z * lw + lb);
        o.w = rna((p.w - mu.w) * rs.w * lw + lb);
        *reinterpret_cast<float4*>(&s[O_TB + c * 136 + t4]) = o;
    }
    __syncthreads();

    // ---- FFN: 4 j-blocks; fc2 accumulates in registers
    float accF2[2][4] = {};
    for (int jb = 0; jb < 4; jb++) {
        float accF1[2][4] = {};
        gemm_loop(s + O_W0, s + O_TB, tt, cc, g, t, accF1);
        __syncthreads();
        // epi F1: gelu -> TXQ (ch-major [64 j][136])
        {
            int o0 = tt + g, o1 = o0 + 8;
            float b0 = fc1b[jb * 64 + o0], b1 = fc1b[jb * 64 + o1];
            #pragma unroll
            for (int nt = 0; nt < 2; nt++) {
                int c0 = cc + 8 * nt + 2 * t;
                float2 v0, v1;
                v0.x = rna(geluf(accF1[nt][0] + b0));
                v0.y = rna(geluf(accF1[nt][1] + b0));
                v1.x = rna(geluf(accF1[nt][2] + b1));
                v1.y = rna(geluf(accF1[nt][3] + b1));
                *reinterpret_cast<float2*>(&s[O_TXQ + o0 * 136 + c0]) = v0;
                *reinterpret_cast<float2*>(&s[O_TXQ + o1 * 136 + c0]) = v1;
            }
        }
        if (jb < 3) stageWT(s + O_W0, fc1w, 256, 64 * (jb + 1), tid);
        __syncthreads();
        gemm_loop(s + O_W1, s + O_TXQ, tt, cc, g, t, accF2);
        __syncthreads();
        if (jb < 3) stageWT(s + O_W1, fc2w + 64 * (jb + 1) * 64, 64, 0, tid);
    }
    // epi F2: hfin = acc + fc2b + h -> TXQ (ch-major); stage cw -> W0 (native [out][in])
    {
        int o0 = tt + g, o1 = o0 + 8;
        float b0 = fc2b[o0], b1 = fc2b[o1];
        #pragma unroll
        for (int nt = 0; nt < 2; nt++) {
            int c0 = cc + 8 * nt + 2 * t;
            float2 h0 = *reinterpret_cast<const float2*>(&s[O_TP + o0 * 136 + c0]);
            float2 h1 = *reinterpret_cast<const float2*>(&s[O_TP + o1 * 136 + c0]);
            float2 v0, v1;
            v0.x = rna(accF2[nt][0] + b0 + h0.x);
            v0.y = rna(accF2[nt][1] + b0 + h0.y);
            v1.x = rna(accF2[nt][2] + b1 + h1.x);
            v1.y = rna(accF2[nt][3] + b1 + h1.y);
            *reinterpret_cast<float2*>(&s[O_TXQ + o0 * 136 + c0]) = v0;
            *reinterpret_cast<float2*>(&s[O_TXQ + o1 * 136 + c0]) = v1;
        }
    }
    #pragma unroll
    for (int i = tid; i < 1024; i += NT) {
        int o = i >> 4, c4 = (i & 15) * 4;
        float4 v = *reinterpret_cast<const float4*>(&cw[o * 64 + c4]);
        float4 r = make_float4(rna(v.x), rna(v.y), rna(v.z), rna(v.w));
        *reinterpret_cast<float4*>(&s[O_W0 + o * 68 + c4]) = r;
    }
    __syncthreads();

    // ---- conv GEMM (B = hfin), epi: + cb + x, FiLM, direct gmem store
    float accC[2][4] = {};
    gemm_loop(s + O_W0, s + O_TXQ, tt, cc, g, t, accC);
    {
        int o0 = tt + g, o1 = o0 + 8;
        float cb0 = cb[o0], cb1 = cb[o1];
        float g0 = s[O_GM + o0], g1 = s[O_GM + o1];
        float bt0 = s[O_BT + o0], bt1 = s[O_BT + o1];
        #pragma unroll
        for (int nt = 0; nt < 2; nt++) {
            int c0 = cc + 8 * nt + 2 * t;
            float2 x0 = *reinterpret_cast<const float2*>(&x[base + (size_t)o0 * NPIX + c0]);
            float2 x1 = *reinterpret_cast<const float2*>(&x[base + (size_t)o1 * NPIX + c0]);
            float v;
            float2 r0, r1;
            v = accC[nt][0] + cb0 + x0.x; r0.x = v + g0 * v + bt0;
            v = accC[nt][1] + cb0 + x0.y; r0.y = v + g0 * v + bt0;
            v = accC[nt][2] + cb1 + x1.x; r1.x = v + g1 * v + bt1;
            v = accC[nt][3] + cb1 + x1.y; r1.y = v + g1 * v + bt1;
            *reinterpret_cast<float2*>(&out[base + (size_t)o0 * NPIX + c0]) = r0;
            *reinterpret_cast<float2*>(&out[base + (size_t)o1 * NPIX + c0]) = r1;
        }
    }
}

// ---------------------------------------------------------------------------
extern "C" void kernel_launch(void* const* d_in, const int* in_sizes, int n_in,
                              void* d_out, int out_size) {
    const float* x    = (const float*)d_in[0];
    const float* te   = (const float*)d_in[1];
    const float* qw   = (const float*)d_in[2];
    const float* qb   = (const float*)d_in[3];
    const float* kw   = (const float*)d_in[4];
    const float* kb   = (const float*)d_in[5];
    const float* vw   = (const float*)d_in[6];
    const float* vb   = (const float*)d_in[7];
    const float* ow   = (const float*)d_in[8];
    const float* ob   = (const float*)d_in[9];
    const float* ln1w = (const float*)d_in[10];
    const float* ln1b = (const float*)d_in[11];
    const float* ln2w = (const float*)d_in[12];
    const float* ln2b = (const float*)d_in[13];
    const float* fc1w = (const float*)d_in[14];
    const float* fc1b = (const float*)d_in[15];
    const float* fc2w = (const float*)d_in[16];
    const float* fc2b = (const float*)d_in[17];
    const float* cw   = (const float*)d_in[18];
    const float* cb   = (const float*)d_in[19];
    const float* m1w  = (const float*)d_in[20];
    const float* m1b  = (const float*)d_in[21];
    const float* m2w  = (const float*)d_in[22];
    const float* m2b  = (const float*)d_in[23];
    float* out = (float*)d_out;

    cudaFuncSetAttribute(fused_kernel, cudaFuncAttributeMaxDynamicSharedMemorySize,
                         SMEM_BYTES);

    pool_kernel<<<2048, 128>>>(te);
    film_kernel<<<8, 128>>>(m1w, m1b, m2w, m2b);
    fused_kernel<<<1024, NT, SMEM_BYTES>>>(x, te, qw, qb, kw, kb, vw, vb, ow, ob,
                                           ln1w, ln1b, ln2w, ln2b, fc1w, fc1b,
                                           fc2w, fc2b, cw, cb, out);
}

// round 9
// speedup vs baseline: 1.3050x; 1.3050x over previous
#include <cuda_runtime.h>
#include <cuda_fp16.h>
#include <math.h>
#include <stdint.h>

#define NPIX 16384
constexpr int NT = 512;

__device__ float g_te[8 * 1024];
__device__ float g_film[8 * 128];

__device__ __forceinline__ uint32_t s2u32(const void* p) {
    uint32_t a;
    asm("{ .reg .u64 t; cvta.to.shared.u64 t, %1; cvt.u32.u64 %0, t; }" : "=r"(a) : "l"(p));
    return a;
}
__device__ __forceinline__ float ex2f(float x) {
    float y; asm("ex2.approx.f32 %0, %1;" : "=f"(y) : "f"(x)); return y;
}
__device__ __forceinline__ float geluf(float v) {
    return 0.5f * v * (1.f + erff(v * 0.70710678118654752f));
}

#define LDSM4(r0, r1, r2, r3, addr)                                             \
    asm volatile("ldmatrix.sync.aligned.m8n8.x4.shared.b16 {%0,%1,%2,%3}, [%4];" \
                 : "=r"(r0), "=r"(r1), "=r"(r2), "=r"(r3) : "r"(addr))
#define MMA16(d, a0, a1, a2, a3, b0, b1)                                         \
    asm volatile("mma.sync.aligned.m16n8k16.row.col.f32.f16.f16.f32 "            \
                 "{%0,%1,%2,%3}, {%4,%5,%6,%7}, {%8,%9}, {%0,%1,%2,%3};"         \
                 : "+f"(d[0]), "+f"(d[1]), "+f"(d[2]), "+f"(d[3])                \
                 : "r"(a0), "r"(a1), "r"(a2), "r"(a3), "r"(b0), "r"(b1))

// D[64][128] = W[64][64] @ Act[128 tok][64]^T ; fp16 tiles stride 72 halves.
// warp: tt=16*(w&3) rows, cc=32*(w>>2) tokens; acc[j] = tokens cc+8j..+7.
__device__ __forceinline__ void gemmF16(uint32_t aB, uint32_t bB, int tt, int cc,
                                        int lane, float acc[4][4]) {
    int ar = tt + (lane & 7) + 8 * ((lane >> 3) & 1), ak = 8 * (lane >> 4);
    int br = cc + (lane & 7) + 8 * (lane >> 4), bk = 8 * ((lane >> 3) & 1);
    uint32_t aA = aB + (uint32_t)((ar * 72 + ak) * 2);
    uint32_t bA0 = bB + (uint32_t)((br * 72 + bk) * 2);
    uint32_t bA1 = bA0 + 16 * 144;
    #pragma unroll
    for (int ks = 0; ks < 4; ks++) {
        uint32_t a0, a1, a2, a3, b0, b1, b2, b3;
        LDSM4(a0, a1, a2, a3, aA + 32 * ks);
        LDSM4(b0, b1, b2, b3, bA0 + 32 * ks);
        MMA16(acc[0], a0, a1, a2, a3, b0, b1);
        MMA16(acc[1], a0, a1, a2, a3, b2, b3);
        LDSM4(b0, b1, b2, b3, bA1 + 32 * ks);
        MMA16(acc[2], a0, a1, a2, a3, b0, b1);
        MMA16(acc[3], a0, a1, a2, a3, b2, b3);
    }
}

__global__ void __launch_bounds__(128) pool_kernel(const float* __restrict__ te) {
    const int tid = threadIdx.x, lane = tid & 31, jc = tid >> 5;
    const int ic = blockIdx.x & 3, c = (blockIdx.x >> 2) & 63, b = blockIdx.x >> 8;
    const float* src = te + ((size_t)(b * 64 + c)) * NPIX + (size_t)(ic * 32) * 128 + tid;
    float acc = 0.f;
    #pragma unroll 8
    for (int r = 0; r < 32; r++) acc += src[r * 128];
    for (int off = 16; off; off >>= 1) acc += __shfl_down_sync(0xffffffffu, acc, off);
    if (lane == 0) g_te[b * 1024 + c * 16 + ic * 4 + jc] = acc * (1.0f / 1024.0f);
}

__global__ void __launch_bounds__(128) film_kernel(
    const float* __restrict__ m1w, const float* __restrict__ m1b,
    const float* __restrict__ m2w, const float* __restrict__ m2b) {
    __shared__ float ste[1024];
    __shared__ float shm[128];
    const int b = blockIdx.x, tid = threadIdx.x;
    for (int i = tid; i < 1024; i += 128) ste[i] = g_te[b * 1024 + i];
    __syncthreads();
    float acc = m1b[tid];
    for (int k = 0; k < 1024; k++) acc = fmaf(ste[k], m1w[k * 128 + tid], acc);
    shm[tid] = acc > 0.f ? acc : 0.01f * acc;
    __syncthreads();
    float acc2 = m2b[tid];
    #pragma unroll 4
    for (int k = 0; k < 128; k++) acc2 = fmaf(shm[k], m2w[k * 128 + tid], acc2);
    g_film[b * 128 + tid] = acc2;
}

// half offsets, all tiles stride 72
constexpr int H_H = 0, H_ACT = 9216, H_XQ = 18432, H_TK = 27648, H_TV = 36864;
constexpr int H_W0 = 46080, H_W1 = 50688, H_F = 55296;  // fm floats after
constexpr int SMEM_BYTES = 55296 * 2 + 384 * 4;          // 112128

__device__ __forceinline__ void stage_w(__half* dst, const float* __restrict__ src,
                                        int RL, int co, int tid) {
    #pragma unroll
    for (int i = tid; i < 2048; i += NT) {
        int o = i & 63, k = (i >> 6) << 1;
        *reinterpret_cast<half2*>(dst + o * 72 + k) =
            __floats2half2_rn(src[k * RL + co + o], src[(k + 1) * RL + co + o]);
    }
}
__device__ __forceinline__ void stage_act(__half* dst, const float* __restrict__ g, int tid) {
    #pragma unroll
    for (int i = tid; i < 4096; i += NT) {
        int tok = i & 127, c = (i >> 7) << 1;
        *reinterpret_cast<half2*>(dst + tok * 72 + c) =
            __floats2half2_rn(g[(size_t)c * NPIX + tok], g[(size_t)(c + 1) * NPIX + tok]);
    }
}

__global__ void __launch_bounds__(NT, 2) fused_kernel(
    const float* __restrict__ x, const float* __restrict__ te,
    const float* __restrict__ qw, const float* __restrict__ qb,
    const float* __restrict__ kw, const float* __restrict__ kb,
    const float* __restrict__ vw, const float* __restrict__ vb,
    const float* __restrict__ ow, const float* __restrict__ ob,
    const float* __restrict__ ln1w, const float* __restrict__ ln1b,
    const float* __restrict__ ln2w, const float* __restrict__ ln2b,
    const float* __restrict__ fc1w, const float* __restrict__ fc1b,
    const float* __restrict__ fc2w, const float* __restrict__ fc2b,
    const float* __restrict__ cw, const float* __restrict__ cb,
    float* __restrict__ out) {
    extern __shared__ __align__(16) __half sh[];
    float* fm = reinterpret_cast<float*>(sh + H_F);  // MU[128] RS[128] GM[64] BT[64]
    const int tid = threadIdx.x;
    const int w = tid >> 5, lane = tid & 31;
    const int g = lane >> 2, t = lane & 3;
    const int tt = 16 * (w & 3), cc = 32 * (w >> 2);
    const int b = blockIdx.x >> 7, row = blockIdx.x & 127;
    const size_t base = (size_t)b * 64 * NPIX + (size_t)row * 128;
    const uint32_t ub = s2u32(sh);
    const int o0 = tt + g, o1 = o0 + 8;

    // A: stage
    stage_act(sh + H_XQ, x + base, tid);
    stage_act(sh + H_H, te + base, tid);
    stage_w(sh + H_TK, qw, 64, 0, tid);
    stage_w(sh + H_W0, kw, 64, 0, tid);
    stage_w(sh + H_W1, vw, 64, 0, tid);
    if (tid < 64) {
        fm[256 + tid] = g_film[b * 128 + tid];
        fm[320 + tid] = g_film[b * 128 + 64 + tid];
    }
    __syncthreads();

    // B: LN1
    {
        int tok = tid >> 2, p = tid & 3;
        const half2* rp = reinterpret_cast<const half2*>(sh + H_H + tok * 72 + p * 16);
        float sum = 0.f, sq = 0.f;
        #pragma unroll
        for (int m = 0; m < 8; m++) {
            float2 v = __half22float2(rp[m]);
            sum += v.x + v.y; sq += v.x * v.x + v.y * v.y;
        }
        sum += __shfl_xor_sync(~0u, sum, 1); sum += __shfl_xor_sync(~0u, sum, 2);
        sq += __shfl_xor_sync(~0u, sq, 1); sq += __shfl_xor_sync(~0u, sq, 2);
        if (p == 0) {
            float mu = sum * (1.f / 64.f);
            fm[tok] = mu;
            fm[128 + tok] = rsqrtf(fmaxf(sq * (1.f / 64.f) - mu * mu, 0.f) + 1e-5f);
        }
    }
    __syncthreads();
    #pragma unroll
    for (int i = tid; i < 4096; i += NT) {
        int tok = i & 127, c = (i >> 7) << 1;
        float2 v = __half22float2(*reinterpret_cast<half2*>(sh + H_H + tok * 72 + c));
        float mu = fm[tok], rs = fm[128 + tok];
        *reinterpret_cast<half2*>(sh + H_ACT + tok * 72 + c) = __floats2half2_rn(
            (v.x - mu) * rs * ln1w[c] + ln1b[c], (v.y - mu) * rs * ln1w[c + 1] + ln1b[c + 1]);
    }
    __syncthreads();

    // C: Q,K,V GEMMs
    {
        const float QS = 0.72134752044448170f;
        float aQ[4][4] = {};
        gemmF16(ub + H_TK * 2, ub + H_ACT * 2, tt, cc, lane, aQ);
        float b0 = qb[o0], b1 = qb[o1];
        #pragma unroll
        for (int j = 0; j < 4; j++) {  // Q -> TV (scaled)
            int tok = cc + 8 * j + 2 * t;
            sh[H_TV + tok * 72 + o0] = __float2half((aQ[j][0] + b0) * QS);
            sh[H_TV + (tok + 1) * 72 + o0] = __float2half((aQ[j][1] + b0) * QS);
            sh[H_TV + tok * 72 + o1] = __float2half((aQ[j][2] + b1) * QS);
            sh[H_TV + (tok + 1) * 72 + o1] = __float2half((aQ[j][3] + b1) * QS);
        }
    }
    float aK[4][4] = {}, aV[4][4] = {};
    gemmF16(ub + H_W0 * 2, ub + H_XQ * 2, tt, cc, lane, aK);
    gemmF16(ub + H_W1 * 2, ub + H_XQ * 2, tt, cc, lane, aV);
    __syncthreads();
    {
        float kb0 = kb[o0], kb1 = kb[o1], vb0 = vb[o0], vb1 = vb[o1];
        #pragma unroll
        for (int j = 0; j < 4; j++) {  // K -> TK, V -> XQ
            int tok = cc + 8 * j + 2 * t;
            sh[H_TK + tok * 72 + o0] = __float2half(aK[j][0] + kb0);
            sh[H_TK + (tok + 1) * 72 + o0] = __float2half(aK[j][1] + kb0);
            sh[H_TK + tok * 72 + o1] = __float2half(aK[j][2] + kb1);
            sh[H_TK + (tok + 1) * 72 + o1] = __float2half(aK[j][3] + kb1);
            sh[H_XQ + tok * 72 + o0] = __float2half(aV[j][0] + vb0);
            sh[H_XQ + (tok + 1) * 72 + o0] = __float2half(aV[j][1] + vb0);
            sh[H_XQ + tok * 72 + o1] = __float2half(aV[j][2] + vb1);
            sh[H_XQ + (tok + 1) * 72 + o1] = __float2half(aV[j][3] + vb1);
        }
    }
    stage_w(sh + H_W1, ow, 64, 0, tid);
    stage_w(sh + H_W0, fc1w, 256, 0, tid);
    __syncthreads();

    // D: attention — warp=head w; Q@TV, K@TK, V@XQ -> ACT
    {
        const int hd = 4 * w;
        uint32_t qA[4], qB[4];
        #pragma unroll
        for (int j = 0; j < 4; j++) {
            int tok = lane + 32 * j;
            qA[j] = *reinterpret_cast<uint32_t*>(sh + H_TV + tok * 72 + hd);
            qB[j] = *reinterpret_cast<uint32_t*>(sh + H_TV + tok * 72 + hd + 2);
        }
        float va[4][4] = {};
        float l[4] = {};
        #pragma unroll 2
        for (int k = 0; k < 128; k++) {
            half2 k01 = *reinterpret_cast<const half2*>(sh + H_TK + k * 72 + hd);
            half2 k23 = *reinterpret_cast<const half2*>(sh + H_TK + k * 72 + hd + 2);
            float2 v01 = __half22float2(*reinterpret_cast<const half2*>(sh + H_XQ + k * 72 + hd));
            float2 v23 = __half22float2(*reinterpret_cast<const half2*>(sh + H_XQ + k * 72 + hd + 2));
            #pragma unroll
            for (int j = 0; j < 4; j++) {
                half2 s2 = __hfma2(*reinterpret_cast<half2*>(&qB[j]), k23,
                                   __hmul2(*reinterpret_cast<half2*>(&qA[j]), k01));
                float e = ex2f(__low2float(s2) + __high2float(s2));
                l[j] += e;
                va[j][0] += e * v01.x; va[j][1] += e * v01.y;
                va[j][2] += e * v23.x; va[j][3] += e * v23.y;
            }
        }
        #pragma unroll
        for (int j = 0; j < 4; j++) {
            int tok = lane + 32 * j;
            float inv = __fdividef(1.f, l[j]);
            *reinterpret_cast<half2*>(sh + H_ACT + tok * 72 + hd) =
                __floats2half2_rn(va[j][0] * inv, va[j][1] * inv);
            *reinterpret_cast<half2*>(sh + H_ACT + tok * 72 + hd + 2) =
                __floats2half2_rn(va[j][2] * inv, va[j][3] * inv);
        }
    }
    __syncthreads();

    // E: O GEMM, h = acc + ob + prior (RMW H)
    {
        float aO[4][4] = {};
        gemmF16(ub + H_W1 * 2, ub + H_ACT * 2, tt, cc, lane, aO);
        float b0 = ob[o0], b1 = ob[o1];
        #pragma unroll
        for (int j = 0; j < 4; j++) {
            int tok = cc + 8 * j + 2 * t;
            #pragma unroll
            for (int d = 0; d < 4; d++) {
                int idx = H_H + (tok + (d & 1)) * 72 + ((d < 2) ? o0 : o1);
                sh[idx] = __float2half(aO[j][d] + ((d < 2) ? b0 : b1) + __half2float(sh[idx]));
            }
        }
    }
    __syncthreads();
    // LN2
    {
        int tok = tid >> 2, p = tid & 3;
        const half2* rp = reinterpret_cast<const half2*>(sh + H_H + tok * 72 + p * 16);
        float sum = 0.f, sq = 0.f;
        #pragma unroll
        for (int m = 0; m < 8; m++) {
            float2 v = __half22float2(rp[m]);
            sum += v.x + v.y; sq += v.x * v.x + v.y * v.y;
        }
        sum += __shfl_xor_sync(~0u, sum, 1); sum += __shfl_xor_sync(~0u, sum, 2);
        sq += __shfl_xor_sync(~0u, sq, 1); sq += __shfl_xor_sync(~0u, sq, 2);
        if (p == 0) {
            float mu = sum * (1.f / 64.f);
            fm[tok] = mu;
            fm[128 + tok] = rsqrtf(fmaxf(sq * (1.f / 64.f) - mu * mu, 0.f) + 1e-5f);
        }
    }
    stage_w(sh + H_W1, fc2w, 64, 0, tid);
    __syncthreads();
    #pragma unroll
    for (int i = tid; i < 4096; i += NT) {
        int tok = i & 127, c = (i >> 7) << 1;
        float2 v = __half22float2(*reinterpret_cast<half2*>(sh + H_H + tok * 72 + c));
        float mu = fm[tok], rs = fm[128 + tok];
        *reinterpret_cast<half2*>(sh + H_ACT + tok * 72 + c) = __floats2half2_rn(
            (v.x - mu) * rs * ln2w[c] + ln2b[c], (v.y - mu) * rs * ln2w[c + 1] + ln2b[c + 1]);
    }
    __syncthreads();

    // F: FFN, fc2 accumulates in regs
    float aF2[4][4] = {};
    for (int jb = 0; jb < 4; jb++) {
        float aF1[4][4] = {};
        gemmF16(ub + H_W0 * 2, ub + H_ACT * 2, tt, cc, lane, aF1);
        __syncthreads();
        {
            float b0 = fc1b[jb * 64 + o0], b1 = fc1b[jb * 64 + o1];
            #pragma unroll
            for (int j = 0; j < 4; j++) {
                int tok = cc + 8 * j + 2 * t;
                sh[H_XQ + tok * 72 + o0] = __float2half(geluf(aF1[j][0] + b0));
                sh[H_XQ + (tok + 1) * 72 + o0] = __float2half(geluf(aF1[j][1] + b0));
                sh[H_XQ + tok * 72 + o1] = __float2half(geluf(aF1[j][2] + b1));
                sh[H_XQ + (tok + 1) * 72 + o1] = __float2half(geluf(aF1[j][3] + b1));
            }
        }
        if (jb < 3) stage_w(sh + H_W0, fc1w, 256, 64 * (jb + 1), tid);
        __syncthreads();
        gemmF16(ub + H_W1 * 2, ub + H_XQ * 2, tt, cc, lane, aF2);
        __syncthreads();
        if (jb < 3) stage_w(sh + H_W1, fc2w + 64 * (jb + 1) * 64, 64, 0, tid);
    }
    // G: hfin -> ACT; stage cw (native [o][k]) -> W0
    {
        float b0 = fc2b[o0], b1 = fc2b[o1];
        #pragma unroll
        for (int j = 0; j < 4; j++) {
            int tok = cc + 8 * j + 2 * t;
            #pragma unroll
            for (int d = 0; d < 4; d++) {
                int tk = tok + (d & 1), o = (d < 2) ? o0 : o1;
                sh[H_ACT + tk * 72 + o] = __float2half(
                    aF2[j][d] + ((d < 2) ? b0 : b1) + __half2float(sh[H_H + tk * 72 + o]));
            }
        }
    }
    #pragma unroll
    for (int i = tid; i < 2048; i += NT) {
        int o = i >> 5, k = (i & 31) << 1;
        *reinterpret_cast<half2*>(sh + H_W0 + o * 72 + k) =
            __floats2half2_rn(cw[o * 64 + k], cw[o * 64 + k + 1]);
    }
    __syncthreads();

    // H: conv GEMM + cb + x + FiLM -> out
    {
        float aC[4][4] = {};
        gemmF16(ub + H_W0 * 2, ub + H_ACT * 2, tt, cc, lane, aC);
        float cb0 = cb[o0], cb1 = cb[o1];
        float g0 = fm[256 + o0], g1 = fm[256 + o1];
        float bt0 = fm[320 + o0], bt1 = fm[320 + o1];
        #pragma unroll
        for (int j = 0; j < 4; j++) {
            int tok = cc + 8 * j + 2 * t;
            float2 x0 = *reinterpret_cast<const float2*>(&x[base + (size_t)o0 * NPIX + tok]);
            float2 x1 = *reinterpret_cast<const float2*>(&x[base + (size_t)o1 * NPIX + tok]);
            float v; float2 r0, r1;
            v = aC[j][0] + cb0 + x0.x; r0.x = v + g0 * v + bt0;
            v = aC[j][1] + cb0 + x0.y; r0.y = v + g0 * v + bt0;
            v = aC[j][2] + cb1 + x1.x; r1.x = v + g1 * v + bt1;
            v = aC[j][3] + cb1 + x1.y; r1.y = v + g1 * v + bt1;
            *reinterpret_cast<float2*>(&out[base + (size_t)o0 * NPIX + tok]) = r0;
            *reinterpret_cast<float2*>(&out[base + (size_t)o1 * NPIX + tok]) = r1;
        }
    }
}

extern "C" void kernel_launch(void* const* d_in, const int* in_sizes, int n_in,
                              void* d_out, int out_size) {
    const float* x = (const float*)d_in[0];
    const float* te = (const float*)d_in[1];
    cudaFuncSetAttribute(fused_kernel, cudaFuncAttributeMaxDynamicSharedMemorySize,
                         SMEM_BYTES);
    pool_kernel<<<2048, 128>>>(te);
    film_kernel<<<8, 128>>>((const float*)d_in[20], (const float*)d_in[21],
                            (const float*)d_in[22], (const float*)d_in[23]);
    fused_kernel<<<1024, NT, SMEM_BYTES>>>(
        x, te, (const float*)d_in[2], (const float*)d_in[3], (const float*)d_in[4],
        (const float*)d_in[5], (const float*)d_in[6], (const float*)d_in[7],
        (const float*)d_in[8], (const float*)d_in[9], (const float*)d_in[10],
        (const float*)d_in[11], (const float*)d_in[12], (const float*)d_in[13],
        (const float*)d_in[14], (const float*)d_in[15], (const float*)d_in[16],
        (const float*)d_in[17], (const float*)d_in[18], (const float*)d_in[19],
        (float*)d_out);
}

// round 10
// speedup vs baseline: 1.4938x; 1.1447x over previous
#include <cuda_runtime.h>
#include <cuda_fp16.h>
#include <math.h>
#include <stdint.h>

#define NPIX 16384
constexpr int NT = 512;

__device__ float g_te[8 * 1024];
__device__ float g_film[8 * 128];

__device__ __forceinline__ uint32_t s2u32(const void* p) {
    uint32_t a;
    asm("{ .reg .u64 t; cvta.to.shared.u64 t, %1; cvt.u32.u64 %0, t; }" : "=r"(a) : "l"(p));
    return a;
}
__device__ __forceinline__ half2 h2exp2_(half2 x) {
    half2 y;
    asm("ex2.approx.f16x2 %0, %1;" : "=r"(*(uint32_t*)&y) : "r"(*(uint32_t*)&x));
    return y;
}
__device__ __forceinline__ float geluf(float v) {
    return 0.5f * v * (1.f + erff(v * 0.70710678118654752f));
}

#define LDSM4(r0, r1, r2, r3, addr)                                             \
    asm volatile("ldmatrix.sync.aligned.m8n8.x4.shared.b16 {%0,%1,%2,%3}, [%4];" \
                 : "=r"(r0), "=r"(r1), "=r"(r2), "=r"(r3) : "r"(addr))
#define MMA16(d, a0, a1, a2, a3, b0, b1)                                         \
    asm volatile("mma.sync.aligned.m16n8k16.row.col.f32.f16.f16.f32 "            \
                 "{%0,%1,%2,%3}, {%4,%5,%6,%7}, {%8,%9}, {%0,%1,%2,%3};"         \
                 : "+f"(d[0]), "+f"(d[1]), "+f"(d[2]), "+f"(d[3])                \
                 : "r"(a0), "r"(a1), "r"(a2), "r"(a3), "r"(b0), "r"(b1))

// D[64][128] = W[64][64] @ Act[128 tok][64]^T ; fp16 tiles stride 72 halves.
__device__ __forceinline__ void gemmF16(uint32_t aB, uint32_t bB, int tt, int cc,
                                        int lane, float acc[4][4]) {
    int ar = tt + (lane & 7) + 8 * ((lane >> 3) & 1), ak = 8 * (lane >> 4);
    int br = cc + (lane & 7) + 8 * (lane >> 4), bk = 8 * ((lane >> 3) & 1);
    uint32_t aA = aB + (uint32_t)((ar * 72 + ak) * 2);
    uint32_t bA0 = bB + (uint32_t)((br * 72 + bk) * 2);
    uint32_t bA1 = bA0 + 16 * 144;
    #pragma unroll
    for (int ks = 0; ks < 4; ks++) {
        uint32_t a0, a1, a2, a3, b0, b1, b2, b3;
        LDSM4(a0, a1, a2, a3, aA + 32 * ks);
        LDSM4(b0, b1, b2, b3, bA0 + 32 * ks);
        MMA16(acc[0], a0, a1, a2, a3, b0, b1);
        MMA16(acc[1], a0, a1, a2, a3, b2, b3);
        LDSM4(b0, b1, b2, b3, bA1 + 32 * ks);
        MMA16(acc[2], a0, a1, a2, a3, b0, b1);
        MMA16(acc[3], a0, a1, a2, a3, b2, b3);
    }
}

__global__ void __launch_bounds__(128) pool_kernel(const float* __restrict__ te) {
    const int tid = threadIdx.x, lane = tid & 31, jc = tid >> 5;
    const int ic = blockIdx.x & 3, c = (blockIdx.x >> 2) & 63, b = blockIdx.x >> 8;
    const float* src = te + ((size_t)(b * 64 + c)) * NPIX + (size_t)(ic * 32) * 128 + tid;
    float acc = 0.f;
    #pragma unroll 8
    for (int r = 0; r < 32; r++) acc += src[r * 128];
    for (int off = 16; off; off >>= 1) acc += __shfl_down_sync(0xffffffffu, acc, off);
    if (lane == 0) g_te[b * 1024 + c * 16 + ic * 4 + jc] = acc * (1.0f / 1024.0f);
}

__global__ void __launch_bounds__(128) film_kernel(
    const float* __restrict__ m1w, const float* __restrict__ m1b,
    const float* __restrict__ m2w, const float* __restrict__ m2b) {
    __shared__ float ste[1024];
    __shared__ float shm[128];
    const int b = blockIdx.x, tid = threadIdx.x;
    for (int i = tid; i < 1024; i += 128) ste[i] = g_te[b * 1024 + i];
    __syncthreads();
    float acc = m1b[tid];
    for (int k = 0; k < 1024; k++) acc = fmaf(ste[k], m1w[k * 128 + tid], acc);
    shm[tid] = acc > 0.f ? acc : 0.01f * acc;
    __syncthreads();
    float acc2 = m2b[tid];
    #pragma unroll 4
    for (int k = 0; k < 128; k++) acc2 = fmaf(shm[k], m2w[k * 128 + tid], acc2);
    g_film[b * 128 + tid] = acc2;
}

// half offsets: token-major tiles stride 72; K'/V'/Q' channel-major [64][136]
constexpr int H_H = 0, H_ACT = 9216, H_XQ = 18432, H_TK = 27648, H_TV = 36864;
constexpr int H_W0 = 46080, H_W1 = 50688, H_F = 55296;
constexpr int SMEM_BYTES = 55296 * 2 + 384 * 4;  // 112128

__device__ __forceinline__ void stage_w(__half* dst, const float* __restrict__ src,
                                        int RL, int co, int tid) {
    #pragma unroll
    for (int i = tid; i < 2048; i += NT) {
        int o = i & 63, k = (i >> 6) << 1;
        *reinterpret_cast<half2*>(dst + o * 72 + k) =
            __floats2half2_rn(src[k * RL + co + o], src[(k + 1) * RL + co + o]);
    }
}
__device__ __forceinline__ void stage_act(__half* dst, const float* __restrict__ g, int tid) {
    #pragma unroll
    for (int i = tid; i < 4096; i += NT) {
        int tok = i & 127, c = (i >> 7) << 1;
        *reinterpret_cast<half2*>(dst + tok * 72 + c) =
            __floats2half2_rn(g[(size_t)c * NPIX + tok], g[(size_t)(c + 1) * NPIX + tok]);
    }
}

__global__ void __launch_bounds__(NT, 2) fused_kernel(
    const float* __restrict__ x, const float* __restrict__ te,
    const float* __restrict__ qw, const float* __restrict__ qb,
    const float* __restrict__ kw, const float* __restrict__ kb,
    const float* __restrict__ vw, const float* __restrict__ vb,
    const float* __restrict__ ow, const float* __restrict__ ob,
    const float* __restrict__ ln1w, const float* __restrict__ ln1b,
    const float* __restrict__ ln2w, const float* __restrict__ ln2b,
    const float* __restrict__ fc1w, const float* __restrict__ fc1b,
    const float* __restrict__ fc2w, const float* __restrict__ fc2b,
    const float* __restrict__ cw, const float* __restrict__ cb,
    float* __restrict__ out) {
    extern __shared__ __align__(16) __half sh[];
    float* fm = reinterpret_cast<float*>(sh + H_F);  // MU[128] RS[128] GM[64] BT[64]
    const int tid = threadIdx.x;
    const int w = tid >> 5, lane = tid & 31;
    const int g = lane >> 2, t = lane & 3;
    const int tt = 16 * (w & 3), cc = 32 * (w >> 2);
    const int b = blockIdx.x >> 7, row = blockIdx.x & 127;
    const size_t base = (size_t)b * 64 * NPIX + (size_t)row * 128;
    const uint32_t ub = s2u32(sh);
    const int o0 = tt + g, o1 = o0 + 8;

    // A: stage
    stage_act(sh + H_XQ, x + base, tid);
    stage_act(sh + H_H, te + base, tid);
    stage_w(sh + H_TK, qw, 64, 0, tid);
    stage_w(sh + H_W0, kw, 64, 0, tid);
    stage_w(sh + H_W1, vw, 64, 0, tid);
    if (tid < 64) {
        fm[256 + tid] = g_film[b * 128 + tid];
        fm[320 + tid] = g_film[b * 128 + 64 + tid];
    }
    __syncthreads();

    // B: LN1
    {
        int tok = tid >> 2, p = tid & 3;
        const half2* rp = reinterpret_cast<const half2*>(sh + H_H + tok * 72 + p * 16);
        float sum = 0.f, sq = 0.f;
        #pragma unroll
        for (int m = 0; m < 8; m++) {
            float2 v = __half22float2(rp[m]);
            sum += v.x + v.y; sq += v.x * v.x + v.y * v.y;
        }
        sum += __shfl_xor_sync(~0u, sum, 1); sum += __shfl_xor_sync(~0u, sum, 2);
        sq += __shfl_xor_sync(~0u, sq, 1); sq += __shfl_xor_sync(~0u, sq, 2);
        if (p == 0) {
            float mu = sum * (1.f / 64.f);
            fm[tok] = mu;
            fm[128 + tok] = rsqrtf(fmaxf(sq * (1.f / 64.f) - mu * mu, 0.f) + 1e-5f);
        }
    }
    __syncthreads();
    #pragma unroll
    for (int i = tid; i < 4096; i += NT) {
        int tok = i & 127, c = (i >> 7) << 1;
        float2 v = __half22float2(*reinterpret_cast<half2*>(sh + H_H + tok * 72 + c));
        float mu = fm[tok], rs = fm[128 + tok];
        *reinterpret_cast<half2*>(sh + H_ACT + tok * 72 + c) = __floats2half2_rn(
            (v.x - mu) * rs * ln1w[c] + ln1b[c], (v.y - mu) * rs * ln1w[c + 1] + ln1b[c + 1]);
    }
    __syncthreads();

    // C: Q,K,V GEMMs; epilogues channel-major [ch][136]
    {
        const float QS = 0.72134752044448170f;
        float aQ[4][4] = {};
        gemmF16(ub + H_TK * 2, ub + H_ACT * 2, tt, cc, lane, aQ);
        float b0 = qb[o0], b1 = qb[o1];
        #pragma unroll
        for (int j = 0; j < 4; j++) {  // Q' -> TV
            int tok = cc + 8 * j + 2 * t;
            *reinterpret_cast<half2*>(sh + H_TV + o0 * 136 + tok) =
                __floats2half2_rn((aQ[j][0] + b0) * QS, (aQ[j][1] + b0) * QS);
            *reinterpret_cast<half2*>(sh + H_TV + o1 * 136 + tok) =
                __floats2half2_rn((aQ[j][2] + b1) * QS, (aQ[j][3] + b1) * QS);
        }
    }
    float aK[4][4] = {}, aV[4][4] = {};
    gemmF16(ub + H_W0 * 2, ub + H_XQ * 2, tt, cc, lane, aK);
    gemmF16(ub + H_W1 * 2, ub + H_XQ * 2, tt, cc, lane, aV);
    __syncthreads();
    {
        float kb0 = kb[o0], kb1 = kb[o1], vb0 = vb[o0], vb1 = vb[o1];
        #pragma unroll
        for (int j = 0; j < 4; j++) {  // K' -> TK, V' -> XQ
            int tok = cc + 8 * j + 2 * t;
            *reinterpret_cast<half2*>(sh + H_TK + o0 * 136 + tok) =
                __floats2half2_rn(aK[j][0] + kb0, aK[j][1] + kb0);
            *reinterpret_cast<half2*>(sh + H_TK + o1 * 136 + tok) =
                __floats2half2_rn(aK[j][2] + kb1, aK[j][3] + kb1);
            *reinterpret_cast<half2*>(sh + H_XQ + o0 * 136 + tok) =
                __floats2half2_rn(aV[j][0] + vb0, aV[j][1] + vb0);
            *reinterpret_cast<half2*>(sh + H_XQ + o1 * 136 + tok) =
                __floats2half2_rn(aV[j][2] + vb1, aV[j][3] + vb1);
        }
    }
    stage_w(sh + H_W1, ow, 64, 0, tid);
    stage_w(sh + H_W0, fc1w, 256, 0, tid);
    __syncthreads();

    // D: attention — warp = head w; K'@TK, V'@XQ, Q'@TV (channel-major)
    {
        const int hd = 4 * w;
        half2 qd[4][4];
        #pragma unroll
        for (int j = 0; j < 4; j++) {
            int tok = lane + 32 * j;
            #pragma unroll
            for (int d = 0; d < 4; d++)
                qd[j][d] = __half2half2(sh[H_TV + (hd + d) * 136 + tok]);
        }
        half2 va[4][4], vl[4];
        #pragma unroll
        for (int j = 0; j < 4; j++) {
            vl[j] = __float2half2_rn(0.f);
            #pragma unroll
            for (int d = 0; d < 4; d++) va[j][d] = __float2half2_rn(0.f);
        }
        float lf[4] = {0.f, 0.f, 0.f, 0.f};
        #pragma unroll 4
        for (int kp = 0; kp < 64; kp++) {
            half2 K0 = *reinterpret_cast<const half2*>(sh + H_TK + (hd + 0) * 136 + 2 * kp);
            half2 K1 = *reinterpret_cast<const half2*>(sh + H_TK + (hd + 1) * 136 + 2 * kp);
            half2 K2 = *reinterpret_cast<const half2*>(sh + H_TK + (hd + 2) * 136 + 2 * kp);
            half2 K3 = *reinterpret_cast<const half2*>(sh + H_TK + (hd + 3) * 136 + 2 * kp);
            half2 V0 = *reinterpret_cast<const half2*>(sh + H_XQ + (hd + 0) * 136 + 2 * kp);
            half2 V1 = *reinterpret_cast<const half2*>(sh + H_XQ + (hd + 1) * 136 + 2 * kp);
            half2 V2 = *reinterpret_cast<const half2*>(sh + H_XQ + (hd + 2) * 136 + 2 * kp);
            half2 V3 = *reinterpret_cast<const half2*>(sh + H_XQ + (hd + 3) * 136 + 2 * kp);
            #pragma unroll
            for (int j = 0; j < 4; j++) {
                half2 s2 = __hfma2(qd[j][3], K3, __hfma2(qd[j][2], K2,
                           __hfma2(qd[j][1], K1, __hmul2(qd[j][0], K0))));
                half2 e2 = h2exp2_(s2);
                vl[j] = __hadd2(vl[j], e2);
                va[j][0] = __hfma2(e2, V0, va[j][0]);
                va[j][1] = __hfma2(e2, V1, va[j][1]);
                va[j][2] = __hfma2(e2, V2, va[j][2]);
                va[j][3] = __hfma2(e2, V3, va[j][3]);
            }
            if ((kp & 3) == 3) {
                #pragma unroll
                for (int j = 0; j < 4; j++) {
                    float2 f = __half22float2(vl[j]);
                    lf[j] += f.x + f.y;
                    vl[j] = __float2half2_rn(0.f);
                }
            }
        }
        #pragma unroll
        for (int j = 0; j < 4; j++) {
            int tok = lane + 32 * j;
            float inv = __fdividef(1.f, lf[j]);
            float2 a0 = __half22float2(va[j][0]);
            float2 a1 = __half22float2(va[j][1]);
            float2 a2 = __half22float2(va[j][2]);
            float2 a3 = __half22float2(va[j][3]);
            *reinterpret_cast<half2*>(sh + H_ACT + tok * 72 + hd) =
                __floats2half2_rn((a0.x + a0.y) * inv, (a1.x + a1.y) * inv);
            *reinterpret_cast<half2*>(sh + H_ACT + tok * 72 + hd + 2) =
                __floats2half2_rn((a2.x + a2.y) * inv, (a3.x + a3.y) * inv);
        }
    }
    __syncthreads();

    // E: O GEMM, h = acc + ob + prior (RMW H)
    {
        float aO[4][4] = {};
        gemmF16(ub + H_W1 * 2, ub + H_ACT * 2, tt, cc, lane, aO);
        float b0 = ob[o0], b1 = ob[o1];
        #pragma unroll
        for (int j = 0; j < 4; j++) {
            int tok = cc + 8 * j + 2 * t;
            #pragma unroll
            for (int d = 0; d < 4; d++) {
                int idx = H_H + (tok + (d & 1)) * 72 + ((d < 2) ? o0 : o1);
                sh[idx] = __float2half(aO[j][d] + ((d < 2) ? b0 : b1) + __half2float(sh[idx]));
            }
        }
    }
    __syncthreads();
    // LN2
    {
        int tok = tid >> 2, p = tid & 3;
        const half2* rp = reinterpret_cast<const half2*>(sh + H_H + tok * 72 + p * 16);
        float sum = 0.f, sq = 0.f;
        #pragma unroll
        for (int m = 0; m < 8; m++) {
            float2 v = __half22float2(rp[m]);
            sum += v.x + v.y; sq += v.x * v.x + v.y * v.y;
        }
        sum += __shfl_xor_sync(~0u, sum, 1); sum += __shfl_xor_sync(~0u, sum, 2);
        sq += __shfl_xor_sync(~0u, sq, 1); sq += __shfl_xor_sync(~0u, sq, 2);
        if (p == 0) {
            float mu = sum * (1.f / 64.f);
            fm[tok] = mu;
            fm[128 + tok] = rsqrtf(fmaxf(sq * (1.f / 64.f) - mu * mu, 0.f) + 1e-5f);
        }
    }
    stage_w(sh + H_W1, fc2w, 64, 0, tid);
    __syncthreads();
    #pragma unroll
    for (int i = tid; i < 4096; i += NT) {
        int tok = i & 127, c = (i >> 7) << 1;
        float2 v = __half22float2(*reinterpret_cast<half2*>(sh + H_H + tok * 72 + c));
        float mu = fm[tok], rs = fm[128 + tok];
        *reinterpret_cast<half2*>(sh + H_ACT + tok * 72 + c) = __floats2half2_rn(
            (v.x - mu) * rs * ln2w[c] + ln2b[c], (v.y - mu) * rs * ln2w[c + 1] + ln2b[c + 1]);
    }
    __syncthreads();

    // F: FFN, fc2 accumulates in regs
    float aF2[4][4] = {};
    for (int jb = 0; jb < 4; jb++) {
        float aF1[4][4] = {};
        gemmF16(ub + H_W0 * 2, ub + H_ACT * 2, tt, cc, lane, aF1);
        __syncthreads();
        {
            float b0 = fc1b[jb * 64 + o0], b1 = fc1b[jb * 64 + o1];
            #pragma unroll
            for (int j = 0; j < 4; j++) {
                int tok = cc + 8 * j + 2 * t;
                sh[H_XQ + tok * 72 + o0] = __float2half(geluf(aF1[j][0] + b0));
                sh[H_XQ + (tok + 1) * 72 + o0] = __float2half(geluf(aF1[j][1] + b0));
                sh[H_XQ + tok * 72 + o1] = __float2half(geluf(aF1[j][2] + b1));
                sh[H_XQ + (tok + 1) * 72 + o1] = __float2half(geluf(aF1[j][3] + b1));
            }
        }
        if (jb < 3) stage_w(sh + H_W0, fc1w, 256, 64 * (jb + 1), tid);
        __syncthreads();
        gemmF16(ub + H_W1 * 2, ub + H_XQ * 2, tt, cc, lane, aF2);
        __syncthreads();
        if (jb < 3) stage_w(sh + H_W1, fc2w + 64 * (jb + 1) * 64, 64, 0, tid);
    }
    // G: hfin -> ACT; stage cw -> W0
    {
        float b0 = fc2b[o0], b1 = fc2b[o1];
        #pragma unroll
        for (int j = 0; j < 4; j++) {
            int tok = cc + 8 * j + 2 * t;
            #pragma unroll
            for (int d = 0; d < 4; d++) {
                int tk = tok + (d & 1), o = (d < 2) ? o0 : o1;
                sh[H_ACT + tk * 72 + o] = __float2half(
                    aF2[j][d] + ((d < 2) ? b0 : b1) + __half2float(sh[H_H + tk * 72 + o]));
            }
        }
    }
    #pragma unroll
    for (int i = tid; i < 2048; i += NT) {
        int o = i >> 5, k = (i & 31) << 1;
        *reinterpret_cast<half2*>(sh + H_W0 + o * 72 + k) =
            __floats2half2_rn(cw[o * 64 + k], cw[o * 64 + k + 1]);
    }
    __syncthreads();

    // H: conv GEMM + cb + x + FiLM -> out
    {
        float aC[4][4] = {};
        gemmF16(ub + H_W0 * 2, ub + H_ACT * 2, tt, cc, lane, aC);
        float cb0 = cb[o0], cb1 = cb[o1];
        float g0 = fm[256 + o0], g1 = fm[256 + o1];
        float bt0 = fm[320 + o0], bt1 = fm[320 + o1];
        #pragma unroll
        for (int j = 0; j < 4; j++) {
            int tok = cc + 8 * j + 2 * t;
            float2 x0 = *reinterpret_cast<const float2*>(&x[base + (size_t)o0 * NPIX + tok]);
            float2 x1 = *reinterpret_cast<const float2*>(&x[base + (size_t)o1 * NPIX + tok]);
            float v; float2 r0, r1;
            v = aC[j][0] + cb0 + x0.x; r0.x = v + g0 * v + bt0;
            v = aC[j][1] + cb0 + x0.y; r0.y = v + g0 * v + bt0;
            v = aC[j][2] + cb1 + x1.x; r1.x = v + g1 * v + bt1;
            v = aC[j][3] + cb1 + x1.y; r1.y = v + g1 * v + bt1;
            *reinterpret_cast<float2*>(&out[base + (size_t)o0 * NPIX + tok]) = r0;
            *reinterpret_cast<float2*>(&out[base + (size_t)o1 * NPIX + tok]) = r1;
        }
    }
}

extern "C" void kernel_launch(void* const* d_in, const int* in_sizes, int n_in,
                              void* d_out, int out_size) {
    const float* x = (const float*)d_in[0];
    const float* te = (const float*)d_in[1];
    cudaFuncSetAttribute(fused_kernel, cudaFuncAttributeMaxDynamicSharedMemorySize,
                         SMEM_BYTES);
    pool_kernel<<<2048, 128>>>(te);
    film_kernel<<<8, 128>>>((const float*)d_in[20], (const float*)d_in[21],
                            (const float*)d_in[22], (const float*)d_in[23]);
    fused_kernel<<<1024, NT, SMEM_BYTES>>>(
        x, te, (const float*)d_in[2], (const float*)d_in[3], (const float*)d_in[4],
        (const float*)d_in[5], (const float*)d_in[6], (const float*)d_in[7],
        (const float*)d_in[8], (const float*)d_in[9], (const float*)d_in[10],
        (const float*)d_in[11], (const float*)d_in[12], (const float*)d_in[13],
        (const float*)d_in[14], (const float*)d_in[15], (const float*)d_in[16],
        (const float*)d_in[17], (const float*)d_in[18], (const float*)d_in[19],
        (float*)d_out);
}

// round 11
// speedup vs baseline: 1.8197x; 1.2181x over previous
#include <cuda_runtime.h>
#include <cuda_fp16.h>
#include <math.h>
#include <stdint.h>

#define NPIX 16384
constexpr int NT = 512;

__device__ float g_te[8 * 1024];
__device__ float g_film[8 * 128];

__device__ __forceinline__ uint32_t s2u32(const void* p) {
    uint32_t a;
    asm("{ .reg .u64 t; cvta.to.shared.u64 t, %1; cvt.u32.u64 %0, t; }" : "=r"(a) : "l"(p));
    return a;
}
__device__ __forceinline__ uint32_t expp(float a, float b) {  // ex2 of packed pair
    half2 h = __floats2half2_rn(a, b);
    uint32_t r;
    asm("ex2.approx.f16x2 %0, %1;" : "=r"(r) : "r"(*(uint32_t*)&h));
    return r;
}
__device__ __forceinline__ half2 u2h(uint32_t u) { return *(half2*)&u; }
__device__ __forceinline__ float geluf(float v) {
    return 0.5f * v * (1.f + erff(v * 0.70710678118654752f));
}

#define LDSM4(r0, r1, r2, r3, addr)                                             \
    asm volatile("ldmatrix.sync.aligned.m8n8.x4.shared.b16 {%0,%1,%2,%3}, [%4];" \
                 : "=r"(r0), "=r"(r1), "=r"(r2), "=r"(r3) : "r"(addr))
#define LDSM2(r0, r1, addr)                                                      \
    asm volatile("ldmatrix.sync.aligned.m8n8.x2.shared.b16 {%0,%1}, [%2];"       \
                 : "=r"(r0), "=r"(r1) : "r"(addr))
#define MMA16(d, a0, a1, a2, a3, b0, b1)                                         \
    asm volatile("mma.sync.aligned.m16n8k16.row.col.f32.f16.f16.f32 "            \
                 "{%0,%1,%2,%3}, {%4,%5,%6,%7}, {%8,%9}, {%0,%1,%2,%3};"         \
                 : "+f"(d[0]), "+f"(d[1]), "+f"(d[2]), "+f"(d[3])                \
                 : "r"(a0), "r"(a1), "r"(a2), "r"(a3), "r"(b0), "r"(b1))
#define MMA8(d, a0, a1, b0)                                                      \
    asm volatile("mma.sync.aligned.m16n8k8.row.col.f32.f16.f16.f32 "             \
                 "{%0,%1,%2,%3}, {%4,%5}, {%6}, {%0,%1,%2,%3};"                  \
                 : "+f"(d[0]), "+f"(d[1]), "+f"(d[2]), "+f"(d[3])                \
                 : "r"(a0), "r"(a1), "r"(b0))

// D[64][128] = W[64][64] @ Act[128 tok][64]^T ; fp16 tiles stride 72 halves.
__device__ __forceinline__ void gemmF16(uint32_t aB, uint32_t bB, int tt, int cc,
                                        int lane, float acc[4][4]) {
    int ar = tt + (lane & 7) + 8 * ((lane >> 3) & 1), ak = 8 * (lane >> 4);
    int br = cc + (lane & 7) + 8 * (lane >> 4), bk = 8 * ((lane >> 3) & 1);
    uint32_t aA = aB + (uint32_t)((ar * 72 + ak) * 2);
    uint32_t bA0 = bB + (uint32_t)((br * 72 + bk) * 2);
    uint32_t bA1 = bA0 + 16 * 144;
    #pragma unroll
    for (int ks = 0; ks < 4; ks++) {
        uint32_t a0, a1, a2, a3, b0, b1, b2, b3;
        LDSM4(a0, a1, a2, a3, aA + 32 * ks);
        LDSM4(b0, b1, b2, b3, bA0 + 32 * ks);
        MMA16(acc[0], a0, a1, a2, a3, b0, b1);
        MMA16(acc[1], a0, a1, a2, a3, b2, b3);
        LDSM4(b0, b1, b2, b3, bA1 + 32 * ks);
        MMA16(acc[2], a0, a1, a2, a3, b0, b1);
        MMA16(acc[3], a0, a1, a2, a3, b2, b3);
    }
}

__global__ void __launch_bounds__(128) pool_kernel(const float* __restrict__ te) {
    const int tid = threadIdx.x, lane = tid & 31, jc = tid >> 5;
    const int ic = blockIdx.x & 3, c = (blockIdx.x >> 2) & 63, b = blockIdx.x >> 8;
    const float* src = te + ((size_t)(b * 64 + c)) * NPIX + (size_t)(ic * 32) * 128 + tid;
    float acc = 0.f;
    #pragma unroll 8
    for (int r = 0; r < 32; r++) acc += src[r * 128];
    for (int off = 16; off; off >>= 1) acc += __shfl_down_sync(0xffffffffu, acc, off);
    if (lane == 0) g_te[b * 1024 + c * 16 + ic * 4 + jc] = acc * (1.0f / 1024.0f);
}

__global__ void __launch_bounds__(128) film_kernel(
    const float* __restrict__ m1w, const float* __restrict__ m1b,
    const float* __restrict__ m2w, const float* __restrict__ m2b) {
    __shared__ float ste[1024];
    __shared__ float shm[128];
    const int b = blockIdx.x, tid = threadIdx.x;
    for (int i = tid; i < 1024; i += 128) ste[i] = g_te[b * 1024 + i];
    __syncthreads();
    float acc = m1b[tid];
    for (int k = 0; k < 1024; k++) acc = fmaf(ste[k], m1w[k * 128 + tid], acc);
    shm[tid] = acc > 0.f ? acc : 0.01f * acc;
    __syncthreads();
    float acc2 = m2b[tid];
    #pragma unroll 4
    for (int k = 0; k < 128; k++) acc2 = fmaf(shm[k], m2w[k * 128 + tid], acc2);
    g_film[b * 128 + tid] = acc2;
}

// half offsets
constexpr int H_H = 0;        // prior -> h        [128][72]
constexpr int H_ACT = 9216;   // LN1 -> attn-out -> hn -> hfin [128][72]
constexpr int H_XQ = 18432;   // x -> Q' tok-major -> gelu [128][72]
constexpr int H_KS = 27648;   // kw|vw|(W slots) -> K_s [16][128][8]   (16384)
constexpr int H_VC = 44032;   // qw stage -> V' channel-major [64][136] (8704)
constexpr int H_F = 52736;    // fm floats: MU[128] RS[128] GM[64] BT[64]
constexpr int SMEM_BYTES = (52736 + 768) * 2;  // 107008

__device__ __forceinline__ void stage_w(__half* dst, const float* __restrict__ src,
                                        int RL, int co, int tid) {
    #pragma unroll
    for (int i = tid; i < 2048; i += NT) {
        int o = i & 63, k = (i >> 6) << 1;
        *reinterpret_cast<half2*>(dst + o * 72 + k) =
            __floats2half2_rn(src[k * RL + co + o], src[(k + 1) * RL + co + o]);
    }
}
__device__ __forceinline__ void stage_act(__half* dst, const float* __restrict__ g, int tid) {
    #pragma unroll
    for (int i = tid; i < 4096; i += NT) {
        int tok = i & 127, c = (i >> 7) << 1;
        *reinterpret_cast<half2*>(dst + tok * 72 + c) =
            __floats2half2_rn(g[(size_t)c * NPIX + tok], g[(size_t)(c + 1) * NPIX + tok]);
    }
}

__global__ void __launch_bounds__(NT, 2) fused_kernel(
    const float* __restrict__ x, const float* __restrict__ te,
    const float* __restrict__ qw, const float* __restrict__ qb,
    const float* __restrict__ kw, const float* __restrict__ kb,
    const float* __restrict__ vw, const float* __restrict__ vb,
    const float* __restrict__ ow, const float* __restrict__ ob,
    const float* __restrict__ ln1w, const float* __restrict__ ln1b,
    const float* __restrict__ ln2w, const float* __restrict__ ln2b,
    const float* __restrict__ fc1w, const float* __restrict__ fc1b,
    const float* __restrict__ fc2w, const float* __restrict__ fc2b,
    const float* __restrict__ cw, const float* __restrict__ cb,
    float* __restrict__ out) {
    extern __shared__ __align__(16) __half sh[];
    float* fm = reinterpret_cast<float*>(sh + H_F);
    const int tid = threadIdx.x;
    const int w = tid >> 5, lane = tid & 31;
    const int g = lane >> 2, t = lane & 3;
    const int tt = 16 * (w & 3), cc = 32 * (w >> 2);
    const int b = blockIdx.x >> 7, row = blockIdx.x & 127;
    const size_t base = (size_t)b * 64 * NPIX + (size_t)row * 128;
    const uint32_t ub = s2u32(sh);
    const int o0 = tt + g, o1 = o0 + 8;

    // A: stage x, prior; kw->KS+0, vw->KS+4608, qw->VC; film
    stage_act(sh + H_XQ, x + base, tid);
    stage_act(sh + H_H, te + base, tid);
    stage_w(sh + H_KS, kw, 64, 0, tid);
    stage_w(sh + H_KS + 4608, vw, 64, 0, tid);
    stage_w(sh + H_VC, qw, 64, 0, tid);
    if (tid < 64) {
        fm[256 + tid] = g_film[b * 128 + tid];
        fm[320 + tid] = g_film[b * 128 + 64 + tid];
    }
    __syncthreads();

    // B: LN1
    {
        int tok = tid >> 2, p = tid & 3;
        const half2* rp = reinterpret_cast<const half2*>(sh + H_H + tok * 72 + p * 16);
        float sum = 0.f, sq = 0.f;
        #pragma unroll
        for (int m = 0; m < 8; m++) {
            float2 v = __half22float2(rp[m]);
            sum += v.x + v.y; sq += v.x * v.x + v.y * v.y;
        }
        sum += __shfl_xor_sync(~0u, sum, 1); sum += __shfl_xor_sync(~0u, sum, 2);
        sq += __shfl_xor_sync(~0u, sq, 1); sq += __shfl_xor_sync(~0u, sq, 2);
        if (p == 0) {
            float mu = sum * (1.f / 64.f);
            fm[tok] = mu;
            fm[128 + tok] = rsqrtf(fmaxf(sq * (1.f / 64.f) - mu * mu, 0.f) + 1e-5f);
        }
    }
    __syncthreads();
    #pragma unroll
    for (int i = tid; i < 4096; i += NT) {
        int tok = i & 127, c = (i >> 7) << 1;
        float2 v = __half22float2(*reinterpret_cast<half2*>(sh + H_H + tok * 72 + c));
        float mu = fm[tok], rs = fm[128 + tok];
        *reinterpret_cast<half2*>(sh + H_ACT + tok * 72 + c) = __floats2half2_rn(
            (v.x - mu) * rs * ln1w[c] + ln1b[c], (v.y - mu) * rs * ln1w[c + 1] + ln1b[c + 1]);
    }
    __syncthreads();

    // C1: K,V GEMMs (read XQ=x, KS weights)
    float aK[4][4] = {}, aV[4][4] = {};
    gemmF16(ub + H_KS * 2, ub + H_XQ * 2, tt, cc, lane, aK);
    gemmF16(ub + (H_KS + 4608) * 2, ub + H_XQ * 2, tt, cc, lane, aV);
    __syncthreads();
    // zero KS (16384 halves)
    #pragma unroll
    for (int i = tid; i < 2048; i += NT)
        reinterpret_cast<uint4*>(sh + H_KS)[i] = make_uint4(0, 0, 0, 0);
    __syncthreads();
    // C2: K epilogue -> K_s (zero-padded); Q GEMM (VC=qw, ACT)
    {
        int h0 = o0 >> 2, s0 = 4 * (h0 & 1) + (o0 & 3);
        int h1 = o1 >> 2, s1 = 4 * (h1 & 1) + (o1 & 3);
        float kb0 = kb[o0], kb1 = kb[o1];
        #pragma unroll
        for (int j = 0; j < 4; j++) {
            int tok = cc + 8 * j + 2 * t;
            sh[H_KS + h0 * 1024 + tok * 8 + s0] = __float2half(aK[j][0] + kb0);
            sh[H_KS + h0 * 1024 + (tok + 1) * 8 + s0] = __float2half(aK[j][1] + kb0);
            sh[H_KS + h1 * 1024 + tok * 8 + s1] = __float2half(aK[j][2] + kb1);
            sh[H_KS + h1 * 1024 + (tok + 1) * 8 + s1] = __float2half(aK[j][3] + kb1);
        }
    }
    float aQ[4][4] = {};
    gemmF16(ub + H_VC * 2, ub + H_ACT * 2, tt, cc, lane, aQ);
    __syncthreads();
    // C3: V -> VC channel-major; Q (scaled) -> XQ token-major
    {
        float vb0 = vb[o0], vb1 = vb[o1];
        const float QS = 0.72134752044448170f;
        float qb0 = qb[o0], qb1 = qb[o1];
        #pragma unroll
        for (int j = 0; j < 4; j++) {
            int tok = cc + 8 * j + 2 * t;
            *reinterpret_cast<half2*>(sh + H_VC + o0 * 136 + tok) =
                __floats2half2_rn(aV[j][0] + vb0, aV[j][1] + vb0);
            *reinterpret_cast<half2*>(sh + H_VC + o1 * 136 + tok) =
                __floats2half2_rn(aV[j][2] + vb1, aV[j][3] + vb1);
            sh[H_XQ + tok * 72 + o0] = __float2half((aQ[j][0] + qb0) * QS);
            sh[H_XQ + (tok + 1) * 72 + o0] = __float2half((aQ[j][1] + qb0) * QS);
            sh[H_XQ + tok * 72 + o1] = __float2half((aQ[j][2] + qb1) * QS);
            sh[H_XQ + (tok + 1) * 72 + o1] = __float2half((aQ[j][3] + qb1) * QS);
        }
    }
    __syncthreads();

    // D: MMA attention — warp = head w
    {
        const int h = w, p8 = (h >> 1) * 8;
        uint32_t kb_[16];
        uint32_t ksb = ub + (uint32_t)(H_KS + h * 1024) * 2 + (uint32_t)((lane & 15) * 16);
        #pragma unroll
        for (int jj = 0; jj < 8; jj++) LDSM2(kb_[2 * jj], kb_[2 * jj + 1], ksb + 256 * jj);
        const uint32_t qbase = ub + (uint32_t)H_XQ * 2 + (uint32_t)(((lane & 15) * 72 + p8) * 2);
        const uint32_t vbase = ub + (uint32_t)(H_VC + (4 * h + (lane & 7)) * 136 +
                                               8 * ((lane >> 3) & 1)) * 2;
        #pragma unroll
        for (int qt = 0; qt < 8; qt++) {
            uint32_t a0, a1;
            LDSM2(a0, a1, qbase + qt * (16 * 144));
            float pv[4] = {0.f, 0.f, 0.f, 0.f};
            half2 lg = __float2half2_rn(0.f), lh = __float2half2_rn(0.f);
            float lfg = 0.f, lfh = 0.f;
            #pragma unroll
            for (int j = 0; j < 8; j++) {
                float c[4] = {0.f, 0.f, 0.f, 0.f}, d[4] = {0.f, 0.f, 0.f, 0.f};
                MMA8(c, a0, a1, kb_[2 * j]);
                MMA8(d, a0, a1, kb_[2 * j + 1]);
                uint32_t e0 = expp(c[0], c[1]), e1 = expp(c[2], c[3]);
                uint32_t e2 = expp(d[0], d[1]), e3 = expp(d[2], d[3]);
                lg = __hadd2(lg, __hadd2(u2h(e0), u2h(e2)));
                lh = __hadd2(lh, __hadd2(u2h(e1), u2h(e3)));
                uint32_t vb0, vb1;
                LDSM2(vb0, vb1, vbase + 32 * j);
                MMA16(pv, e0, e1, e2, e3, vb0, vb1);
                if ((j & 3) == 3) {
                    float2 f = __half22float2(lg); lfg += f.x + f.y;
                    f = __half22float2(lh); lfh += f.x + f.y;
                    lg = __float2half2_rn(0.f); lh = __float2half2_rn(0.f);
                }
            }
            lfg += __shfl_xor_sync(~0u, lfg, 1); lfg += __shfl_xor_sync(~0u, lfg, 2);
            lfh += __shfl_xor_sync(~0u, lfh, 1); lfh += __shfl_xor_sync(~0u, lfh, 2);
            float ig = __fdividef(1.f, lfg), ih = __fdividef(1.f, lfh);
            if (t < 2) {
                int tokg = 16 * qt + g;
                *reinterpret_cast<half2*>(sh + H_ACT + tokg * 72 + 4 * h + 2 * t) =
                    __floats2half2_rn(pv[0] * ig, pv[1] * ig);
                *reinterpret_cast<half2*>(sh + H_ACT + (tokg + 8) * 72 + 4 * h + 2 * t) =
                    __floats2half2_rn(pv[2] * ih, pv[3] * ih);
            }
        }
    }
    __syncthreads();
    stage_w(sh + H_KS, ow, 64, 0, tid);
    __syncthreads();

    // E: O GEMM, h = acc + ob + prior (RMW H)
    {
        float aO[4][4] = {};
        gemmF16(ub + H_KS * 2, ub + H_ACT * 2, tt, cc, lane, aO);
        float b0 = ob[o0], b1 = ob[o1];
        #pragma unroll
        for (int j = 0; j < 4; j++) {
            int tok = cc + 8 * j + 2 * t;
            #pragma unroll
            for (int d = 0; d < 4; d++) {
                int idx = H_H + (tok + (d & 1)) * 72 + ((d < 2) ? o0 : o1);
                sh[idx] = __float2half(aO[j][d] + ((d < 2) ? b0 : b1) + __half2float(sh[idx]));
            }
        }
    }
    __syncthreads();
    // LN2
    {
        int tok = tid >> 2, p = tid & 3;
        const half2* rp = reinterpret_cast<const half2*>(sh + H_H + tok * 72 + p * 16);
        float sum = 0.f, sq = 0.f;
        #pragma unroll
        for (int m = 0; m < 8; m++) {
            float2 v = __half22float2(rp[m]);
            sum += v.x + v.y; sq += v.x * v.x + v.y * v.y;
        }
        sum += __shfl_xor_sync(~0u, sum, 1); sum += __shfl_xor_sync(~0u, sum, 2);
        sq += __shfl_xor_sync(~0u, sq, 1); sq += __shfl_xor_sync(~0u, sq, 2);
        if (p == 0) {
            float mu = sum * (1.f / 64.f);
            fm[tok] = mu;
            fm[128 + tok] = rsqrtf(fmaxf(sq * (1.f / 64.f) - mu * mu, 0.f) + 1e-5f);
        }
    }
    stage_w(sh + H_KS + 4608, fc1w, 256, 0, tid);
    stage_w(sh + H_KS + 9216, fc2w, 64, 0, tid);
    __syncthreads();
    #pragma unroll
    for (int i = tid; i < 4096; i += NT) {
        int tok = i & 127, c = (i >> 7) << 1;
        float2 v = __half22float2(*reinterpret_cast<half2*>(sh + H_H + tok * 72 + c));
        float mu = fm[tok], rs = fm[128 + tok];
        *reinterpret_cast<half2*>(sh + H_ACT + tok * 72 + c) = __floats2half2_rn(
            (v.x - mu) * rs * ln2w[c] + ln2b[c], (v.y - mu) * rs * ln2w[c + 1] + ln2b[c + 1]);
    }
    __syncthreads();

    // F: FFN
    float aF2[4][4] = {};
    for (int jb = 0; jb < 4; jb++) {
        float aF1[4][4] = {};
        gemmF16(ub + (H_KS + 4608) * 2, ub + H_ACT * 2, tt, cc, lane, aF1);
        __syncthreads();
        {
            float b0 = fc1b[jb * 64 + o0], b1 = fc1b[jb * 64 + o1];
            #pragma unroll
            for (int j = 0; j < 4; j++) {
                int tok = cc + 8 * j + 2 * t;
                sh[H_XQ + tok * 72 + o0] = __float2half(geluf(aF1[j][0] + b0));
                sh[H_XQ + (tok + 1) * 72 + o0] = __float2half(geluf(aF1[j][1] + b0));
                sh[H_XQ + tok * 72 + o1] = __float2half(geluf(aF1[j][2] + b1));
                sh[H_XQ + (tok + 1) * 72 + o1] = __float2half(geluf(aF1[j][3] + b1));
            }
        }
        if (jb < 3) stage_w(sh + H_KS + 4608, fc1w, 256, 64 * (jb + 1), tid);
        __syncthreads();
        gemmF16(ub + (H_KS + 9216) * 2, ub + H_XQ * 2, tt, cc, lane, aF2);
        __syncthreads();
        if (jb < 3) stage_w(sh + H_KS + 9216, fc2w + 64 * (jb + 1) * 64, 64, 0, tid);
    }
    // G: hfin -> ACT; stage cw -> KS+0
    {
        float b0 = fc2b[o0], b1 = fc2b[o1];
        #pragma unroll
        for (int j = 0; j < 4; j++) {
            int tok = cc + 8 * j + 2 * t;
            #pragma unroll
            for (int d = 0; d < 4; d++) {
                int tk = tok + (d & 1), o = (d < 2) ? o0 : o1;
                sh[H_ACT + tk * 72 + o] = __float2half(
                    aF2[j][d] + ((d < 2) ? b0 : b1) + __half2float(sh[H_H + tk * 72 + o]));
            }
        }
    }
    #pragma unroll
    for (int i = tid; i < 2048; i += NT) {
        int o = i >> 5, k = (i & 31) << 1;
        *reinterpret_cast<half2*>(sh + H_KS + o * 72 + k) =
            __floats2half2_rn(cw[o * 64 + k], cw[o * 64 + k + 1]);
    }
    __syncthreads();

    // H: conv GEMM + cb + x + FiLM -> out
    {
        float aC[4][4] = {};
        gemmF16(ub + H_KS * 2, ub + H_ACT * 2, tt, cc, lane, aC);
        float cb0 = cb[o0], cb1 = cb[o1];
        float g0 = fm[256 + o0], g1 = fm[256 + o1];
        float bt0 = fm[320 + o0], bt1 = fm[320 + o1];
        #pragma unroll
        for (int j = 0; j < 4; j++) {
            int tok = cc + 8 * j + 2 * t;
            float2 x0 = *reinterpret_cast<const float2*>(&x[base + (size_t)o0 * NPIX + tok]);
            float2 x1 = *reinterpret_cast<const float2*>(&x[base + (size_t)o1 * NPIX + tok]);
            float v; float2 r0, r1;
            v = aC[j][0] + cb0 + x0.x; r0.x = v + g0 * v + bt0;
            v = aC[j][1] + cb0 + x0.y; r0.y = v + g0 * v + bt0;
            v = aC[j][2] + cb1 + x1.x; r1.x = v + g1 * v + bt1;
            v = aC[j][3] + cb1 + x1.y; r1.y = v + g1 * v + bt1;
            *reinterpret_cast<float2*>(&out[base + (size_t)o0 * NPIX + tok]) = r0;
            *reinterpret_cast<float2*>(&out[base + (size_t)o1 * NPIX + tok]) = r1;
        }
    }
}

extern "C" void kernel_launch(void* const* d_in, const int* in_sizes, int n_in,
                              void* d_out, int out_size) {
    const float* x = (const float*)d_in[0];
    const float* te = (const float*)d_in[1];
    cudaFuncSetAttribute(fused_kernel, cudaFuncAttributeMaxDynamicSharedMemorySize,
                         SMEM_BYTES);
    pool_kernel<<<2048, 128>>>(te);
    film_kernel<<<8, 128>>>((const float*)d_in[20], (const float*)d_in[21],
                            (const float*)d_in[22], (const float*)d_in[23]);
    fused_kernel<<<1024, NT, SMEM_BYTES>>>(
        x, te, (const float*)d_in[2], (const float*)d_in[3], (const float*)d_in[4],
        (const float*)d_in[5], (const float*)d_in[6], (const float*)d_in[7],
        (const float*)d_in[8], (const float*)d_in[9], (const float*)d_in[10],
        (const float*)d_in[11], (const float*)d_in[12], (const float*)d_in[13],
        (const float*)d_in[14], (const float*)d_in[15], (const float*)d_in[16],
        (const float*)d_in[17], (const float*)d_in[18], (const float*)d_in[19],
        (float*)d_out);
}